// round 6
// baseline (speedup 1.0000x reference)
#include <cuda_runtime.h>
#include <cstdint>

#define TND 65536   // T * N_
#define NDIM 256    // DIMS
#define NKEY 64     // M

// Output section offsets (flattened tuple, fp32)
#define OFF_UPMEM 33554432ull   // 512*65536
#define OFF_SQ    33570816ull
#define OFF_SM    37765120ull
#define OFF_SPR   41959424ull
#define OFF_GTH   42024960ull

// Scratch (device globals: allocation-free)
__device__ float    g_score[(size_t)TND * NKEY];   // 16 MB
__device__ float    g_qupd[NKEY * NDIM];
__device__ unsigned g_cmax[NKEY];                  // order-encoded float max
__device__ float    g_csum[NKEY];

typedef unsigned long long ull;

__device__ __forceinline__ ull pack2(float lo, float hi) {
    ull r; asm("mov.b64 %0, {%1,%2};" : "=l"(r) : "f"(lo), "f"(hi)); return r;
}
__device__ __forceinline__ void unpack2(ull v, float& lo, float& hi) {
    asm("mov.b64 {%0,%1}, %2;" : "=f"(lo), "=f"(hi) : "l"(v));
}
__device__ __forceinline__ ull fma2(ull a, ull b, ull c) {
    ull d; asm("fma.rn.f32x2 %0, %1, %2, %3;" : "=l"(d) : "l"(a), "l"(b), "l"(c)); return d;
}
// order-preserving float<->uint encoding for atomicMax on signed floats
__device__ __forceinline__ unsigned fenc(float f) {
    unsigned u = __float_as_uint(f);
    return (u & 0x80000000u) ? ~u : (u | 0x80000000u);
}
__device__ __forceinline__ float fdec(unsigned e) {
    return (e & 0x80000000u) ? __uint_as_float(e & 0x7FFFFFFFu) : __uint_as_float(~e);
}

__global__ void k_init() {
    int t = blockIdx.x * blockDim.x + threadIdx.x;
    if (t < NKEY * NDIM) g_qupd[t] = 0.f;
    if (t < NKEY) { g_cmax[t] = 0x007FFFFFu; /* enc(-inf) */ g_csum[t] = 0.f; }
}

// K1: score[i][m] = sum_d query[d][i] * keys[m][d]; fused per-column max.
__global__ __launch_bounds__(256, 2) void k_score(const float* __restrict__ query,
                                                  const float* __restrict__ keys) {
    extern __shared__ float sm1[];        // keysT[256][64], reused as wmax[8][64]
    float* keysT = sm1;
    int tid = threadIdx.x;
    for (int idx = tid; idx < NKEY * NDIM; idx += 256) {
        int m = idx >> 8, d = idx & 255;
        keysT[d * NKEY + m] = keys[idx];
    }
    __syncthreads();

    int i = blockIdx.x * 256 + tid;
    ull acc[32];
#pragma unroll
    for (int j = 0; j < 32; j++) acc[j] = 0ull;

#pragma unroll 4
    for (int d = 0; d < NDIM; d++) {
        float q = __ldg(query + (size_t)d * TND + i);
        ull qq = pack2(q, q);
        const ulonglong2* kt = (const ulonglong2*)(keysT + d * NKEY);
#pragma unroll
        for (int j = 0; j < 16; j++) {
            ulonglong2 kk = kt[j];
            acc[2 * j]     = fma2(qq, kk.x, acc[2 * j]);
            acc[2 * j + 1] = fma2(qq, kk.y, acc[2 * j + 1]);
        }
    }

    ull* srow = (ull*)(g_score + (size_t)i * NKEY);
#pragma unroll
    for (int j = 0; j < 32; j++) srow[j] = acc[j];

    __syncthreads();   // done with keysT; reuse smem for warp maxima
    float* wmax = sm1; // [8][64]
    int w = tid >> 5, lane = tid & 31;
#pragma unroll
    for (int j = 0; j < 32; j++) {
        float a, b; unpack2(acc[j], a, b);
#pragma unroll
        for (int o = 16; o; o >>= 1) {
            a = fmaxf(a, __shfl_xor_sync(0xffffffffu, a, o));
            b = fmaxf(b, __shfl_xor_sync(0xffffffffu, b, o));
        }
        if (lane == 0) { wmax[w * NKEY + 2 * j] = a; wmax[w * NKEY + 2 * j + 1] = b; }
    }
    __syncthreads();
    if (tid < NKEY) {
        float mx = wmax[tid];
#pragma unroll
        for (int ww = 1; ww < 8; ww++) mx = fmaxf(mx, wmax[ww * NKEY + tid]);
        atomicMax(&g_cmax[tid], fenc(mx));
    }
}

// K2: colsum[m] = sum_i exp(score[i][m] - colmax[m])
__global__ __launch_bounds__(256) void k_colsum() {
    __shared__ float cmax[NKEY];
    __shared__ float wsum[8][NKEY];
    int tid = threadIdx.x;
    if (tid < NKEY) cmax[tid] = fdec(g_cmax[tid]);
    __syncthreads();
    int i = blockIdx.x * 256 + tid;
    const float4* s4 = (const float4*)(g_score + (size_t)i * NKEY);
    int w = tid >> 5, lane = tid & 31;
#pragma unroll
    for (int j = 0; j < 16; j++) {
        float4 f = s4[j];
        float e0 = __expf(f.x - cmax[4 * j]);
        float e1 = __expf(f.y - cmax[4 * j + 1]);
        float e2 = __expf(f.z - cmax[4 * j + 2]);
        float e3 = __expf(f.w - cmax[4 * j + 3]);
#pragma unroll
        for (int o = 16; o; o >>= 1) {
            e0 += __shfl_xor_sync(~0u, e0, o); e1 += __shfl_xor_sync(~0u, e1, o);
            e2 += __shfl_xor_sync(~0u, e2, o); e3 += __shfl_xor_sync(~0u, e3, o);
        }
        if (lane == 0) {
            wsum[w][4 * j] = e0; wsum[w][4 * j + 1] = e1;
            wsum[w][4 * j + 2] = e2; wsum[w][4 * j + 3] = e3;
        }
    }
    __syncthreads();
    if (tid < NKEY) {
        float s = 0.f;
#pragma unroll
        for (int ww = 0; ww < 8; ww++) s += wsum[ww][tid];
        atomicAdd(&g_csum[tid], s);
    }
}

// K3: everything per-row: top2, both softmaxes, gathering, triplet, concat GEMV,
// query_update accumulation (smem, 257-stride pad), transposed concat writes.
__global__ __launch_bounds__(256, 1) void k_main(const float* __restrict__ query,
                                                 const float* __restrict__ keys,
                                                 float* __restrict__ out) {
    extern __shared__ float sm3[];
    float* skeys  = sm3;           // [64][256]  (broadcast layout for concat)
    float* skeysT = sm3 + 16384;   // [256][64]  (per-thread-g layout, conflict-free)
    float* sacc   = sm3 + 32768;   // [64][257]  query_update accumulator
    float* scmax  = sm3 + 49216;   // [64]
    float* scsinv = sm3 + 49280;   // [64]
    int tid = threadIdx.x;
    for (int idx = tid; idx < NKEY * NDIM; idx += 256) {
        float v = keys[idx];
        skeys[idx] = v;
        int m = idx >> 8, d = idx & 255;
        skeysT[d * NKEY + m] = v;
    }
    for (int idx = tid; idx < NKEY * 257; idx += 256) sacc[idx] = 0.f;
    if (tid < NKEY) { scmax[tid] = fdec(g_cmax[tid]); scsinv[tid] = 1.f / g_csum[tid]; }
    __syncthreads();

    int i = blockIdx.x * 256 + tid;
    const float4* s4 = (const float4*)(g_score + (size_t)i * NKEY);

    // pass 1: rowmax + top2 indices
    float v1 = -3.4e38f, v2 = -3.4e38f; int g1 = 0, g2 = 0;
#pragma unroll
    for (int j = 0; j < 16; j++) {
        float4 f = s4[j];
        float vv[4] = {f.x, f.y, f.z, f.w};
#pragma unroll
        for (int k = 0; k < 4; k++) {
            float s = vv[k]; int m = 4 * j + k;
            if (s > v1) { v2 = v1; g2 = g1; v1 = s; g1 = m; }
            else if (s > v2) { v2 = s; g2 = m; }
        }
    }
    float rowmax = v1;

    // pass 2: exps, score_query written directly; keep row-softmax numerators
    float smr[64];
    float rowsum = 0.f;
    float4* sqout = (float4*)(out + OFF_SQ + (size_t)i * NKEY);
#pragma unroll
    for (int j = 0; j < 16; j++) {
        float4 f = s4[j];
        float e0 = __expf(f.x - rowmax), e1 = __expf(f.y - rowmax);
        float e2 = __expf(f.z - rowmax), e3 = __expf(f.w - rowmax);
        smr[4 * j] = e0; smr[4 * j + 1] = e1; smr[4 * j + 2] = e2; smr[4 * j + 3] = e3;
        rowsum += (e0 + e1) + (e2 + e3);
        float4 sq;
        sq.x = __expf(f.x - scmax[4 * j])     * scsinv[4 * j];
        sq.y = __expf(f.y - scmax[4 * j + 1]) * scsinv[4 * j + 1];
        sq.z = __expf(f.z - scmax[4 * j + 2]) * scsinv[4 * j + 2];
        sq.w = __expf(f.w - scmax[4 * j + 3]) * scsinv[4 * j + 3];
        sqout[j] = sq;
    }
    float inv = 1.f / rowsum;
    float4* smout = (float4*)(out + OFF_SM + (size_t)i * NKEY);
#pragma unroll
    for (int j = 0; j < 16; j++) {
        float4 o;
        o.x = smr[4 * j] * inv;     o.y = smr[4 * j + 1] * inv;
        o.z = smr[4 * j + 2] * inv; o.w = smr[4 * j + 3] * inv;
        smr[4 * j] = o.x; smr[4 * j + 1] = o.y; smr[4 * j + 2] = o.z; smr[4 * j + 3] = o.w;
        smout[j] = o;
    }

    // scatter weight: score[i][g1] == rowmax
    float w = __expf(rowmax - scmax[g1]);

    float dpos2 = 0.f, dneg2 = 0.f;
    float* gout = out + OFF_GTH + (size_t)i * NDIM;
    float* cout = out + (size_t)NDIM * TND + i;   // concat half, stride TND over d
    float* saccg = sacc + g1 * 257;

    for (int c = 0; c < 32; c++) {
        int d0 = c * 8;
        float q[8];
#pragma unroll
        for (int k = 0; k < 8; k++) q[k] = __ldg(query + (size_t)(d0 + k) * TND + i);

        // concat_memory chunk: c2 covers d0..d0+7 as 4 packed pairs
        ull c2[4] = {0ull, 0ull, 0ull, 0ull};
#pragma unroll
        for (int m = 0; m < NKEY; m++) {
            const ulonglong2* kp = (const ulonglong2*)(skeys + m * NDIM + d0);
            ulonglong2 ka = kp[0], kb = kp[1];
            ull a = pack2(smr[m], smr[m]);
            c2[0] = fma2(a, ka.x, c2[0]);
            c2[1] = fma2(a, ka.y, c2[1]);
            c2[2] = fma2(a, kb.x, c2[2]);
            c2[3] = fma2(a, kb.y, c2[3]);
        }
#pragma unroll
        for (int j = 0; j < 4; j++) {
            float lo, hi; unpack2(c2[j], lo, hi);
            cout[(size_t)(d0 + 2 * j) * TND]     = lo;   // coalesced across lanes
            cout[(size_t)(d0 + 2 * j + 1) * TND] = hi;
        }

        // gathering loss + triplet distances + query_update accumulation
        float gbuf[8];
#pragma unroll
        for (int k = 0; k < 8; k++) {
            int d = d0 + k;
            float kp = skeysT[d * NKEY + g1];
            float kn = skeysT[d * NKEY + g2];
            float dq = q[k] - kp;
            gbuf[k] = dq * dq;
            float tp = dq + 1e-6f;          dpos2 = fmaf(tp, tp, dpos2);
            float tn = (q[k] - kn) + 1e-6f; dneg2 = fmaf(tn, tn, dneg2);
            atomicAdd(saccg + d, w * q[k]);
        }
        *(float4*)(gout + d0)     = make_float4(gbuf[0], gbuf[1], gbuf[2], gbuf[3]);
        *(float4*)(gout + d0 + 4) = make_float4(gbuf[4], gbuf[5], gbuf[6], gbuf[7]);
    }

    out[OFF_SPR + i] = fmaxf(sqrtf(dpos2) - sqrtf(dneg2) + 1.f, 0.f);

    __syncthreads();
    for (int idx = tid; idx < NKEY * NDIM; idx += 256) {
        int m = idx >> 8, d = idx & 255;
        atomicAdd(&g_qupd[idx], sacc[m * 257 + d]);
    }
}

// K4: updated_memory = l2_normalize(query_update + keys)
__global__ void k_mem(const float* __restrict__ keys, float* __restrict__ out) {
    int m = blockIdx.x, d = threadIdx.x;
    float v = g_qupd[m * NDIM + d] + keys[m * NDIM + d];
    float s = v * v;
#pragma unroll
    for (int o = 16; o; o >>= 1) s += __shfl_xor_sync(~0u, s, o);
    __shared__ float red[8];
    __shared__ float snrm;
    if ((d & 31) == 0) red[d >> 5] = s;
    __syncthreads();
    if (d == 0) {
        float t = 0.f;
        for (int ww = 0; ww < 8; ww++) t += red[ww];
        snrm = fmaxf(sqrtf(t), 1e-12f);
    }
    __syncthreads();
    out[OFF_UPMEM + (size_t)m * NDIM + d] = v / snrm;
}

extern "C" void kernel_launch(void* const* d_in, const int* in_sizes, int n_in,
                              void* d_out, int out_size) {
    const float* query = (const float*)d_in[0];
    const float* keys  = (const float*)d_in[1];
    float* out = (float*)d_out;

    cudaFuncSetAttribute(k_score, cudaFuncAttributeMaxDynamicSharedMemorySize, 64 * 1024);
    cudaFuncSetAttribute(k_main,  cudaFuncAttributeMaxDynamicSharedMemorySize, 49344 * 4);

    // updated_query first half == query verbatim
    cudaMemcpyAsync(d_out, d_in[0], (size_t)TND * NDIM * sizeof(float),
                    cudaMemcpyDeviceToDevice, 0);

    k_init<<<64, 256>>>();
    k_score<<<256, 256, 64 * 1024>>>(query, keys);
    k_colsum<<<256, 256>>>();
    k_main<<<256, 256, 49344 * 4>>>(query, keys, out);
    k_mem<<<64, 256>>>(keys, out);
}

// round 8
// speedup vs baseline: 1.2908x; 1.2908x over previous
#include <cuda_runtime.h>
#include <cstdint>

#define TND 65536   // T * N_
#define NDIM 256    // DIMS
#define NKEY 64     // M

// Output section offsets (flattened tuple, fp32)
#define OFF_UPMEM 33554432ull   // 512*65536
#define OFF_SQ    33570816ull
#define OFF_SM    37765120ull
#define OFF_SPR   41959424ull
#define OFF_GTH   42024960ull

#define ROWS_PER_CTA 443        // ceil(65536/148)

// Scratch (device globals: allocation-free)
__device__ float    g_score[(size_t)TND * NKEY];   // 16 MB
__device__ __align__(16) float g_qupd[NKEY * NDIM];
__device__ unsigned g_cmax[NKEY];                  // order-encoded float max
__device__ float    g_csum[NKEY];

typedef unsigned long long ull;

__device__ __forceinline__ ull pack2(float lo, float hi) {
    ull r; asm("mov.b64 %0, {%1,%2};" : "=l"(r) : "f"(lo), "f"(hi)); return r;
}
__device__ __forceinline__ void unpack2(ull v, float& lo, float& hi) {
    asm("mov.b64 {%0,%1}, %2;" : "=f"(lo), "=f"(hi) : "l"(v));
}
__device__ __forceinline__ ull fma2(ull a, ull b, ull c) {
    ull d; asm("fma.rn.f32x2 %0, %1, %2, %3;" : "=l"(d) : "l"(a), "l"(b), "l"(c)); return d;
}
// order-preserving float<->uint encoding for atomicMax on signed floats
__device__ __forceinline__ unsigned fenc(float f) {
    unsigned u = __float_as_uint(f);
    return (u & 0x80000000u) ? ~u : (u | 0x80000000u);
}
__device__ __forceinline__ float fdec(unsigned e) {
    return (e & 0x80000000u) ? __uint_as_float(e & 0x7FFFFFFFu) : __uint_as_float(~e);
}

__global__ void k_init() {
    int t = blockIdx.x * blockDim.x + threadIdx.x;
    if (t < NKEY * NDIM) g_qupd[t] = 0.f;
    if (t < NKEY) { g_cmax[t] = 0x007FFFFFu; /* enc(-inf) */ g_csum[t] = 0.f; }
}

// K1: score[i][m] = sum_d query[d][i] * keys[m][d]; fused per-column max.
__global__ __launch_bounds__(256, 2) void k_score(const float* __restrict__ query,
                                                  const float* __restrict__ keys) {
    extern __shared__ float sm1[];        // keysT[256][64], reused as wmax[8][64]
    float* keysT = sm1;
    int tid = threadIdx.x;
    for (int idx = tid; idx < NKEY * NDIM; idx += 256) {
        int m = idx >> 8, d = idx & 255;
        keysT[d * NKEY + m] = keys[idx];
    }
    __syncthreads();

    int i = blockIdx.x * 256 + tid;
    ull acc[32];
#pragma unroll
    for (int j = 0; j < 32; j++) acc[j] = 0ull;

#pragma unroll 4
    for (int d = 0; d < NDIM; d++) {
        float q = __ldg(query + (size_t)d * TND + i);
        ull qq = pack2(q, q);
        const ulonglong2* kt = (const ulonglong2*)(keysT + d * NKEY);
#pragma unroll
        for (int j = 0; j < 16; j++) {
            ulonglong2 kk = kt[j];
            acc[2 * j]     = fma2(qq, kk.x, acc[2 * j]);
            acc[2 * j + 1] = fma2(qq, kk.y, acc[2 * j + 1]);
        }
    }

    ull* srow = (ull*)(g_score + (size_t)i * NKEY);
#pragma unroll
    for (int j = 0; j < 32; j++) srow[j] = acc[j];

    __syncthreads();   // done with keysT; reuse smem for warp maxima
    float* wmax = sm1; // [8][64]
    int w = tid >> 5, lane = tid & 31;
#pragma unroll
    for (int j = 0; j < 32; j++) {
        float a, b; unpack2(acc[j], a, b);
#pragma unroll
        for (int o = 16; o; o >>= 1) {
            a = fmaxf(a, __shfl_xor_sync(0xffffffffu, a, o));
            b = fmaxf(b, __shfl_xor_sync(0xffffffffu, b, o));
        }
        if (lane == 0) { wmax[w * NKEY + 2 * j] = a; wmax[w * NKEY + 2 * j + 1] = b; }
    }
    __syncthreads();
    if (tid < NKEY) {
        float mx = wmax[tid];
#pragma unroll
        for (int ww = 1; ww < 8; ww++) mx = fmaxf(mx, wmax[ww * NKEY + tid]);
        atomicMax(&g_cmax[tid], fenc(mx));
    }
}

// K2: colsum[m] = sum_i exp(score[i][m] - colmax[m])
__global__ __launch_bounds__(256) void k_colsum() {
    __shared__ float cmax[NKEY];
    __shared__ float wsum[8][NKEY];
    int tid = threadIdx.x;
    if (tid < NKEY) cmax[tid] = fdec(g_cmax[tid]);
    __syncthreads();
    int i = blockIdx.x * 256 + tid;
    const float4* s4 = (const float4*)(g_score + (size_t)i * NKEY);
    int w = tid >> 5, lane = tid & 31;
#pragma unroll
    for (int j = 0; j < 16; j++) {
        float4 f = s4[j];
        float e0 = __expf(f.x - cmax[4 * j]);
        float e1 = __expf(f.y - cmax[4 * j + 1]);
        float e2 = __expf(f.z - cmax[4 * j + 2]);
        float e3 = __expf(f.w - cmax[4 * j + 3]);
#pragma unroll
        for (int o = 16; o; o >>= 1) {
            e0 += __shfl_xor_sync(~0u, e0, o); e1 += __shfl_xor_sync(~0u, e1, o);
            e2 += __shfl_xor_sync(~0u, e2, o); e3 += __shfl_xor_sync(~0u, e3, o);
        }
        if (lane == 0) {
            wsum[w][4 * j] = e0; wsum[w][4 * j + 1] = e1;
            wsum[w][4 * j + 2] = e2; wsum[w][4 * j + 3] = e3;
        }
    }
    __syncthreads();
    if (tid < NKEY) {
        float s = 0.f;
#pragma unroll
        for (int ww = 0; ww < 8; ww++) s += wsum[ww][tid];
        atomicAdd(&g_csum[tid], s);
    }
}

// K3: per-row: top2, both softmaxes, gathering, triplet, concat GEMV,
// query_update via global vector RED atomics, fused first-half query copy.
__global__ __launch_bounds__(256, 1) void k_main(const float* __restrict__ query,
                                                 const float* __restrict__ keys,
                                                 float* __restrict__ out) {
    extern __shared__ float sm3[];
    float* skeys  = sm3;           // [64][256]  (broadcast layout for concat)
    float* skeysT = sm3 + 16384;   // [256][64]  (per-thread-g layout, low-conflict)
    float* scmax  = sm3 + 32768;   // [64]
    float* scsinv = sm3 + 32832;   // [64]
    int tid = threadIdx.x;
    for (int idx = tid; idx < NKEY * NDIM; idx += 256) {
        float v = keys[idx];
        skeys[idx] = v;
        int m = idx >> 8, d = idx & 255;
        skeysT[d * NKEY + m] = v;
    }
    if (tid < NKEY) { scmax[tid] = fdec(g_cmax[tid]); scsinv[tid] = 1.f / g_csum[tid]; }
    __syncthreads();

    int rstart = blockIdx.x * ROWS_PER_CTA;
    int rend = rstart + ROWS_PER_CTA;
    if (rend > TND) rend = TND;

    for (int i = rstart + tid; i < rend; i += 256) {
        const float4* s4 = (const float4*)(g_score + (size_t)i * NKEY);

        // pass 1: rowmax + top2 indices
        float v1 = -3.4e38f, v2 = -3.4e38f; int g1 = 0, g2 = 0;
#pragma unroll
        for (int j = 0; j < 16; j++) {
            float4 f = s4[j];
            float vv[4] = {f.x, f.y, f.z, f.w};
#pragma unroll
            for (int k = 0; k < 4; k++) {
                float s = vv[k]; int m = 4 * j + k;
                if (s > v1) { v2 = v1; g2 = g1; v1 = s; g1 = m; }
                else if (s > v2) { v2 = s; g2 = m; }
            }
        }
        float rowmax = v1;

        // pass 2: exps, score_query written directly; keep row-softmax numerators
        float smr[64];
        float rowsum = 0.f;
        float4* sqout = (float4*)(out + OFF_SQ + (size_t)i * NKEY);
#pragma unroll
        for (int j = 0; j < 16; j++) {
            float4 f = s4[j];
            float e0 = __expf(f.x - rowmax), e1 = __expf(f.y - rowmax);
            float e2 = __expf(f.z - rowmax), e3 = __expf(f.w - rowmax);
            smr[4 * j] = e0; smr[4 * j + 1] = e1; smr[4 * j + 2] = e2; smr[4 * j + 3] = e3;
            rowsum += (e0 + e1) + (e2 + e3);
            float4 sq;
            sq.x = __expf(f.x - scmax[4 * j])     * scsinv[4 * j];
            sq.y = __expf(f.y - scmax[4 * j + 1]) * scsinv[4 * j + 1];
            sq.z = __expf(f.z - scmax[4 * j + 2]) * scsinv[4 * j + 2];
            sq.w = __expf(f.w - scmax[4 * j + 3]) * scsinv[4 * j + 3];
            sqout[j] = sq;
        }
        float inv = 1.f / rowsum;
        float4* smout = (float4*)(out + OFF_SM + (size_t)i * NKEY);
#pragma unroll
        for (int j = 0; j < 16; j++) {
            float4 o;
            o.x = smr[4 * j] * inv;     o.y = smr[4 * j + 1] * inv;
            o.z = smr[4 * j + 2] * inv; o.w = smr[4 * j + 3] * inv;
            smr[4 * j] = o.x; smr[4 * j + 1] = o.y; smr[4 * j + 2] = o.z; smr[4 * j + 3] = o.w;
            smout[j] = o;
        }

        // scatter weight: score[i][g1] == rowmax
        float w = __expf(rowmax - scmax[g1]);

        float dpos2 = 0.f, dneg2 = 0.f;
        float* gout = out + OFF_GTH + (size_t)i * NDIM;
        float* qout = out + i;                        // updated_query first half
        float* cout = out + (size_t)NDIM * TND + i;   // concat half, stride TND over d
        float* qup  = g_qupd + g1 * NDIM;

        for (int c = 0; c < 32; c++) {
            int d0 = c * 8;
            float q[8];
#pragma unroll
            for (int k = 0; k < 8; k++) q[k] = __ldg(query + (size_t)(d0 + k) * TND + i);

            // fused updated_query first-half copy (replaces the D2D memcpy)
#pragma unroll
            for (int k = 0; k < 8; k++) qout[(size_t)(d0 + k) * TND] = q[k];

            // concat_memory chunk: c2 covers d0..d0+7 as 4 packed pairs
            ull c2[4] = {0ull, 0ull, 0ull, 0ull};
#pragma unroll
            for (int m = 0; m < NKEY; m++) {
                const ulonglong2* kp = (const ulonglong2*)(skeys + m * NDIM + d0);
                ulonglong2 ka = kp[0], kb = kp[1];
                ull a = pack2(smr[m], smr[m]);
                c2[0] = fma2(a, ka.x, c2[0]);
                c2[1] = fma2(a, ka.y, c2[1]);
                c2[2] = fma2(a, kb.x, c2[2]);
                c2[3] = fma2(a, kb.y, c2[3]);
            }
#pragma unroll
            for (int j = 0; j < 4; j++) {
                float lo, hi; unpack2(c2[j], lo, hi);
                cout[(size_t)(d0 + 2 * j) * TND]     = lo;   // coalesced across lanes
                cout[(size_t)(d0 + 2 * j + 1) * TND] = hi;
            }

            // gathering loss + triplet distances + query_update contribution
            float gbuf[8], wq[8];
#pragma unroll
            for (int k = 0; k < 8; k++) {
                int d = d0 + k;
                float kp = skeysT[d * NKEY + g1];
                float kn = skeysT[d * NKEY + g2];
                float dq = q[k] - kp;
                gbuf[k] = dq * dq;
                float tp = dq + 1e-6f;          dpos2 = fmaf(tp, tp, dpos2);
                float tn = (q[k] - kn) + 1e-6f; dneg2 = fmaf(tn, tn, dneg2);
                wq[k] = w * q[k];
            }
            *(float4*)(gout + d0)     = make_float4(gbuf[0], gbuf[1], gbuf[2], gbuf[3]);
            *(float4*)(gout + d0 + 4) = make_float4(gbuf[4], gbuf[5], gbuf[6], gbuf[7]);

            // vector RED atomics into global accumulator (sm_90+ float4 atomicAdd)
            atomicAdd((float4*)(qup + d0),     make_float4(wq[0], wq[1], wq[2], wq[3]));
            atomicAdd((float4*)(qup + d0 + 4), make_float4(wq[4], wq[5], wq[6], wq[7]));
        }

        out[OFF_SPR + i] = fmaxf(sqrtf(dpos2) - sqrtf(dneg2) + 1.f, 0.f);
    }
}

// K4: updated_memory = l2_normalize(query_update + keys)
__global__ void k_mem(const float* __restrict__ keys, float* __restrict__ out) {
    int m = blockIdx.x, d = threadIdx.x;
    float v = g_qupd[m * NDIM + d] + keys[m * NDIM + d];
    float s = v * v;
#pragma unroll
    for (int o = 16; o; o >>= 1) s += __shfl_xor_sync(~0u, s, o);
    __shared__ float red[8];
    __shared__ float snrm;
    if ((d & 31) == 0) red[d >> 5] = s;
    __syncthreads();
    if (d == 0) {
        float t = 0.f;
        for (int ww = 0; ww < 8; ww++) t += red[ww];
        snrm = fmaxf(sqrtf(t), 1e-12f);
    }
    __syncthreads();
    out[OFF_UPMEM + (size_t)m * NDIM + d] = v / snrm;
}

extern "C" void kernel_launch(void* const* d_in, const int* in_sizes, int n_in,
                              void* d_out, int out_size) {
    const float* query = (const float*)d_in[0];
    const float* keys  = (const float*)d_in[1];
    float* out = (float*)d_out;

    cudaFuncSetAttribute(k_score, cudaFuncAttributeMaxDynamicSharedMemorySize, 64 * 1024);
    cudaFuncSetAttribute(k_main,  cudaFuncAttributeMaxDynamicSharedMemorySize, 32896 * 4);

    k_init<<<64, 256>>>();
    k_score<<<256, 256, 64 * 1024>>>(query, keys);
    k_colsum<<<256, 256>>>();
    k_main<<<148, 256, 32896 * 4>>>(query, keys, out);
    k_mem<<<64, 256>>>(keys, out);
}